// round 7
// baseline (speedup 1.0000x reference)
#include <cuda_runtime.h>
#include <cstdint>

// out = Wlat^T X  +  sigmoid(gate) * softmax(X Wa X^T) X Wb
//   Wa[k][n] = sum_e Wq[e,k] Wk[e,n] / 16     (fragment-major in g_Wa_f)
//   Wb[k][n] = sum_e Wo[n,e] Wv[e,k]          (fragment-major in g_Wb_f)
// B=8, T=2048, P=13, D=256; warp = 1 token (padded to 16 rows), 8 warps/CTA.

#define THREADS 256
#define SXR 260       // X smem row stride (fp32)
#define SCB 68        // chunk buffer stride (16 x 64)
#define SAT 20        // attn stride (16 x 16)
#define P1BLK 2176    // 32x64 panel, lane-major stride 68
#define P1PAIR 4352   // two consecutive 32-row panels
#define P2PAN 4224    // 32x128 panel, lane-major stride 132

#define SM_X 0                 // 8*16*260 = 33280
#define SM_P 33280             // 2*4352 = 8704 (ph2 uses 2*4224 <= 8704)
#define SM_C 41984             // 8*16*68 = 8704
#define SM_A 50688             // 8*16*20 = 2560
#define SM_W 53248             // 320
#define SMEM_FLOATS 53568
#define SMEM_BYTES (SMEM_FLOATS * 4)

__device__ float g_Wa_f[32 * P1BLK];   // 32 panels (nc*8+kp)
__device__ float g_Wb_f[16 * P2PAN];   // 16 panels (nh*8+dc*2+kp2)

__device__ __forceinline__ uint32_t f2tf(float x) {
    uint32_t r;
    asm("cvt.rna.tf32.f32 %0, %1;" : "=r"(r) : "f"(x));
    return r;
}
__device__ __forceinline__ float f2tff(float x) {
    return __uint_as_float(f2tf(x));
}

__device__ __forceinline__ void mma8(float* d,
                                     uint32_t a0, uint32_t a1, uint32_t a2, uint32_t a3,
                                     uint32_t b0, uint32_t b1) {
    asm volatile(
        "mma.sync.aligned.m16n8k8.row.col.f32.tf32.tf32.f32 "
        "{%0,%1,%2,%3},{%4,%5,%6,%7},{%8,%9},{%0,%1,%2,%3};\n"
        : "+f"(d[0]), "+f"(d[1]), "+f"(d[2]), "+f"(d[3])
        : "r"(a0), "r"(a1), "r"(a2), "r"(a3), "r"(b0), "r"(b1));
}

// ------------------------------- setup --------------------------------------
// Computes Wa/Wb and scatters straight into fragment-major layout.
__global__ void lc_setup(const float* __restrict__ Wq, const float* __restrict__ Wk,
                         const float* __restrict__ Wv, const float* __restrict__ Wo) {
    int n = threadIdx.x;
    int k = blockIdx.x;
    if (blockIdx.y == 0) {
        float acc = 0.f;
        for (int e = 0; e < 256; ++e)
            acc += Wq[e * 256 + k] * Wk[e * 256 + n];
        acc *= (1.0f / 16.0f);
        int kp = k >> 5, r = k & 31;
        int ks = r >> 3, t7 = r & 7, tg = t7 & 3, j = t7 >> 2;
        int nc = n >> 6, nt = (n >> 3) & 7, g = n & 7;
        g_Wa_f[(nc * 8 + kp) * P1BLK + ((g << 2) + tg) * 68 + ks * 16 + nt * 2 + j] =
            f2tff(acc);
    } else {
        float acc = 0.f;
        for (int e = 0; e < 256; ++e)
            acc += Wo[n * 256 + e] * Wv[e * 256 + k];
        int dc = k >> 6, kp2 = (k >> 5) & 1, r = k & 31;
        int ks = r >> 3, t7 = r & 7, tg = t7 & 3, j = t7 >> 2;
        int nh = n >> 7, nt = (n >> 3) & 15, g = n & 7;
        g_Wb_f[(nh * 8 + dc * 2 + kp2) * P2PAN + ((g << 2) + tg) * 132 + ks * 32 + nt * 2 + j] =
            f2tff(acc);
    }
}

// -------------------------------- main --------------------------------------
__global__ void __launch_bounds__(THREADS, 1)
lc_main(const float* __restrict__ h, const float* __restrict__ Wlat,
        const float* __restrict__ gate, float* __restrict__ out) {
    extern __shared__ float smem[];
    const int tid = threadIdx.x;
    const int w = tid >> 5, lane = tid & 31;
    const int g = lane >> 2, tg = lane & 3;
    const long token = (long)blockIdx.x * 8 + w;

    float* Xs = smem + SM_X + w * 16 * SXR;
    float* Cb = smem + SM_C + w * 16 * SCB;
    float* As = smem + SM_A + w * 16 * SAT;
    float* Wls = smem + SM_W;

    // ---- load X (13x256 fp32), zero pad rows 13..15 ----
    const float* hx = h + token * 3328;
    for (int i = lane; i < 832; i += 32) {
        int row = i >> 6, c4 = (i & 63) << 2;
        *(float4*)(Xs + row * SXR + c4) = *(const float4*)(hx + row * 256 + c4);
    }
    for (int i = lane; i < 768; i += 32) {
        int row = 13 + (i >> 8), c = i & 255;
        Xs[row * SXR + c] = 0.f;
    }
    if (tid < 208) {
        int p = tid >> 4, r = tid & 15;
        Wls[p * 16 + r] = (r < 13) ? Wlat[p * 13 + r] : 0.f;
    }
    float sig;
    { float gv = gate[0]; sig = 1.f / (1.f + __expf(-gv)); }
    __syncthreads();

    // =================== phase 1: Y = X Wa, S = Y X^T ===================
    float s0[4] = {0, 0, 0, 0}, s1[4] = {0, 0, 0, 0};

    for (int nc = 0; nc < 4; ++nc) {
        float ya[8][4];
#pragma unroll
        for (int i = 0; i < 8; ++i)
#pragma unroll
            for (int j = 0; j < 4; ++j) ya[i][j] = 0.f;

        // initial pair (K rows 0..63) -> buf0
        {
            const float* src = g_Wa_f + (nc * 8) * P1BLK;
            for (int idx = tid; idx < 1088; idx += THREADS)
                *(float4*)(smem + SM_P + idx * 4) = *(const float4*)(src + idx * 4);
        }
        __syncthreads();

        for (int pr = 0; pr < 4; ++pr) {
            float4 pf[5];
            if (pr < 3) {
                const float* src = g_Wa_f + (nc * 8 + (pr + 1) * 2) * P1BLK;
#pragma unroll
                for (int t = 0; t < 5; ++t) {
                    int idx = tid + t * THREADS;
                    if (idx < 1088) pf[t] = *(const float4*)(src + idx * 4);
                }
            }
            const float* cur = smem + SM_P + (pr & 1) * P1PAIR + lane * 68;
#pragma unroll
            for (int hf = 0; hf < 2; ++hf) {
                const float* c2 = cur + hf * P1BLK;
#pragma unroll
                for (int ks = 0; ks < 4; ++ks) {
                    int kc = pr * 64 + hf * 32 + ks * 8;
                    uint32_t a0 = f2tf(Xs[g * SXR + kc + tg]);
                    uint32_t a1 = f2tf(Xs[(g + 8) * SXR + kc + tg]);
                    uint32_t a2 = f2tf(Xs[g * SXR + kc + tg + 4]);
                    uint32_t a3 = f2tf(Xs[(g + 8) * SXR + kc + tg + 4]);
                    float4 f0 = *(const float4*)(c2 + ks * 16);
                    float4 f1 = *(const float4*)(c2 + ks * 16 + 4);
                    float4 f2v = *(const float4*)(c2 + ks * 16 + 8);
                    float4 f3v = *(const float4*)(c2 + ks * 16 + 12);
                    mma8(ya[0], a0, a1, a2, a3, __float_as_uint(f0.x), __float_as_uint(f0.y));
                    mma8(ya[1], a0, a1, a2, a3, __float_as_uint(f0.z), __float_as_uint(f0.w));
                    mma8(ya[2], a0, a1, a2, a3, __float_as_uint(f1.x), __float_as_uint(f1.y));
                    mma8(ya[3], a0, a1, a2, a3, __float_as_uint(f1.z), __float_as_uint(f1.w));
                    mma8(ya[4], a0, a1, a2, a3, __float_as_uint(f2v.x), __float_as_uint(f2v.y));
                    mma8(ya[5], a0, a1, a2, a3, __float_as_uint(f2v.z), __float_as_uint(f2v.w));
                    mma8(ya[6], a0, a1, a2, a3, __float_as_uint(f3v.x), __float_as_uint(f3v.y));
                    mma8(ya[7], a0, a1, a2, a3, __float_as_uint(f3v.z), __float_as_uint(f3v.w));
                }
            }
            if (pr < 3) {
                float* nxt = smem + SM_P + ((pr + 1) & 1) * P1PAIR;
#pragma unroll
                for (int t = 0; t < 5; ++t) {
                    int idx = tid + t * THREADS;
                    if (idx < 1088) *(float4*)(nxt + idx * 4) = pf[t];
                }
            }
            __syncthreads();
        }

        // Ychunk -> Cb (tf32), S += Ychunk * Xchunk^T
        __syncwarp();
#pragma unroll
        for (int nt = 0; nt < 8; ++nt) {
            int c = nt * 8 + 2 * tg;
            *(float2*)(Cb + g * SCB + c) = make_float2(f2tff(ya[nt][0]), f2tff(ya[nt][1]));
            *(float2*)(Cb + (g + 8) * SCB + c) = make_float2(f2tff(ya[nt][2]), f2tff(ya[nt][3]));
        }
        __syncwarp();
#pragma unroll
        for (int ks = 0; ks < 8; ++ks) {
            uint32_t a0 = __float_as_uint(Cb[g * SCB + ks * 8 + tg]);
            uint32_t a1 = __float_as_uint(Cb[(g + 8) * SCB + ks * 8 + tg]);
            uint32_t a2 = __float_as_uint(Cb[g * SCB + ks * 8 + tg + 4]);
            uint32_t a3 = __float_as_uint(Cb[(g + 8) * SCB + ks * 8 + tg + 4]);
            int xc = nc * 64 + ks * 8;
            uint32_t b0 = f2tf(Xs[g * SXR + xc + tg]);
            uint32_t b1 = f2tf(Xs[g * SXR + xc + tg + 4]);
            mma8(s0, a0, a1, a2, a3, b0, b1);
            uint32_t c0 = f2tf(Xs[(g + 8) * SXR + xc + tg]);
            uint32_t c1 = f2tf(Xs[(g + 8) * SXR + xc + tg + 4]);
            mma8(s1, a0, a1, a2, a3, c0, c1);
        }
        __syncwarp();
    }

    // =================== softmax over cols 0..12 (sig folded in) ============
    {
        int c0 = 2 * tg, c1 = 2 * tg + 1, c2 = 8 + 2 * tg, c3 = 9 + 2 * tg;
        bool v0 = c0 < 13, v1 = c1 < 13, v2 = c2 < 13, v3 = c3 < 13;
        const float NEG = -1e30f;
        float m0 = fmaxf(fmaxf(v0 ? s0[0] : NEG, v1 ? s0[1] : NEG),
                         fmaxf(v2 ? s1[0] : NEG, v3 ? s1[1] : NEG));
        float m1 = fmaxf(fmaxf(v0 ? s0[2] : NEG, v1 ? s0[3] : NEG),
                         fmaxf(v2 ? s1[2] : NEG, v3 ? s1[3] : NEG));
        m0 = fmaxf(m0, __shfl_xor_sync(0xffffffffu, m0, 1));
        m0 = fmaxf(m0, __shfl_xor_sync(0xffffffffu, m0, 2));
        m1 = fmaxf(m1, __shfl_xor_sync(0xffffffffu, m1, 1));
        m1 = fmaxf(m1, __shfl_xor_sync(0xffffffffu, m1, 2));
        float e00 = v0 ? __expf(s0[0] - m0) : 0.f;
        float e01 = v1 ? __expf(s0[1] - m0) : 0.f;
        float e02 = v2 ? __expf(s1[0] - m0) : 0.f;
        float e03 = v3 ? __expf(s1[1] - m0) : 0.f;
        float e10 = v0 ? __expf(s0[2] - m1) : 0.f;
        float e11 = v1 ? __expf(s0[3] - m1) : 0.f;
        float e12 = v2 ? __expf(s1[2] - m1) : 0.f;
        float e13 = v3 ? __expf(s1[3] - m1) : 0.f;
        float d0 = e00 + e01 + e02 + e03;
        float d1 = e10 + e11 + e12 + e13;
        d0 += __shfl_xor_sync(0xffffffffu, d0, 1);
        d0 += __shfl_xor_sync(0xffffffffu, d0, 2);
        d1 += __shfl_xor_sync(0xffffffffu, d1, 1);
        d1 += __shfl_xor_sync(0xffffffffu, d1, 2);
        float r0 = sig / d0, r1 = sig / d1;
        As[g * SAT + c0]       = f2tff(e00 * r0);
        As[g * SAT + c1]       = f2tff(e01 * r0);
        As[g * SAT + c2]       = f2tff(e02 * r0);
        As[g * SAT + c3]       = f2tff(e03 * r0);
        As[(g + 8) * SAT + c0] = f2tff(e10 * r1);
        As[(g + 8) * SAT + c1] = f2tff(e11 * r1);
        As[(g + 8) * SAT + c2] = f2tff(e12 * r1);
        As[(g + 8) * SAT + c3] = f2tff(e13 * r1);
        __syncwarp();
    }

    // =========== phase 2: Z = (sig*A) X (chunked), R = Z Wb, epilogue =======
    const long obase = token * 3328;
    for (int nh = 0; nh < 2; ++nh) {
        float ra[16][4];
#pragma unroll
        for (int i = 0; i < 16; ++i)
#pragma unroll
            for (int j = 0; j < 4; ++j) ra[i][j] = 0.f;

        // initial panel (ip=0) -> buf0
        {
            const float* src = g_Wb_f + (nh * 8) * P2PAN;
            for (int idx = tid; idx < 1056; idx += THREADS)
                *(float4*)(smem + SM_P + idx * 4) = *(const float4*)(src + idx * 4);
        }
        __syncthreads();

        int ip = 0;
        for (int dc = 0; dc < 4; ++dc) {
            // Zchunk = (sig*A) * X[:, dc*64 .. +64)
            float za[8][4];
#pragma unroll
            for (int i = 0; i < 8; ++i)
#pragma unroll
                for (int j = 0; j < 4; ++j) za[i][j] = 0.f;
#pragma unroll
            for (int ks = 0; ks < 2; ++ks) {
                uint32_t a0 = __float_as_uint(As[g * SAT + ks * 8 + tg]);
                uint32_t a1 = __float_as_uint(As[(g + 8) * SAT + ks * 8 + tg]);
                uint32_t a2 = __float_as_uint(As[g * SAT + ks * 8 + tg + 4]);
                uint32_t a3 = __float_as_uint(As[(g + 8) * SAT + ks * 8 + tg + 4]);
#pragma unroll
                for (int nt = 0; nt < 8; ++nt) {
                    int xc = dc * 64 + nt * 8 + g;
                    uint32_t b0 = f2tf(Xs[(ks * 8 + tg) * SXR + xc]);
                    uint32_t b1 = f2tf(Xs[(ks * 8 + tg + 4) * SXR + xc]);
                    mma8(za[nt], a0, a1, a2, a3, b0, b1);
                }
            }
            __syncwarp();
#pragma unroll
            for (int nt = 0; nt < 8; ++nt) {
                int c = nt * 8 + 2 * tg;
                *(float2*)(Cb + g * SCB + c) = make_float2(f2tff(za[nt][0]), f2tff(za[nt][1]));
                *(float2*)(Cb + (g + 8) * SCB + c) = make_float2(f2tff(za[nt][2]), f2tff(za[nt][3]));
            }
            __syncwarp();

            for (int kp2 = 0; kp2 < 2; ++kp2, ++ip) {
                float4 pf[5];
                if (ip < 7) {
                    const float* src = g_Wb_f + (nh * 8 + ip + 1) * P2PAN;
#pragma unroll
                    for (int t = 0; t < 5; ++t) {
                        int idx = tid + t * THREADS;
                        if (idx < 1056) pf[t] = *(const float4*)(src + idx * 4);
                    }
                }
                const float* cur = smem + SM_P + (ip & 1) * P2PAN + lane * 132;
#pragma unroll
                for (int ks = 0; ks < 4; ++ks) {
                    int kc = kp2 * 32 + ks * 8;
                    uint32_t a0 = __float_as_uint(Cb[g * SCB + kc + tg]);
                    uint32_t a1 = __float_as_uint(Cb[(g + 8) * SCB + kc + tg]);
                    uint32_t a2 = __float_as_uint(Cb[g * SCB + kc + tg + 4]);
                    uint32_t a3 = __float_as_uint(Cb[(g + 8) * SCB + kc + tg + 4]);
#pragma unroll
                    for (int wv = 0; wv < 8; ++wv) {
                        float4 f = *(const float4*)(cur + ks * 32 + wv * 4);
                        mma8(ra[2 * wv], a0, a1, a2, a3,
                             __float_as_uint(f.x), __float_as_uint(f.y));
                        mma8(ra[2 * wv + 1], a0, a1, a2, a3,
                             __float_as_uint(f.z), __float_as_uint(f.w));
                    }
                }
                if (ip < 7) {
                    float* nxt = smem + SM_P + ((ip + 1) & 1) * P2PAN;
#pragma unroll
                    for (int t = 0; t < 5; ++t) {
                        int idx = tid + t * THREADS;
                        if (idx < 1056) *(float4*)(nxt + idx * 4) = pf[t];
                    }
                }
                __syncthreads();
            }
        }

        // ---- epilogue: exact fp32 residual accumulated into ra, then store ----
#pragma unroll 1
        for (int p = 0; p < 13; ++p) {
            float wg = Wls[p * 16 + g];
            float wg8 = Wls[p * 16 + g + 8];
#pragma unroll
            for (int nt = 0; nt < 16; ++nt) {
                int c = nh * 128 + nt * 8 + 2 * tg;
                float2 x = *(float2*)(Xs + p * SXR + c);
                ra[nt][0] += wg * x.x;
                ra[nt][1] += wg * x.y;
                ra[nt][2] += wg8 * x.x;
                ra[nt][3] += wg8 * x.y;
            }
        }
#pragma unroll
        for (int nt = 0; nt < 16; ++nt) {
            int c = nh * 128 + nt * 8 + 2 * tg;
            *(float2*)(out + obase + g * 256 + c) = make_float2(ra[nt][0], ra[nt][1]);
            if (g < 5)
                *(float2*)(out + obase + (g + 8) * 256 + c) = make_float2(ra[nt][2], ra[nt][3]);
        }
    }
}

// ------------------------------ launch --------------------------------------
extern "C" void kernel_launch(void* const* d_in, const int* in_sizes, int n_in,
                              void* d_out, int out_size) {
    const float* h    = (const float*)d_in[0];
    const float* Wq   = (const float*)d_in[1];
    const float* Wk   = (const float*)d_in[2];
    const float* Wv   = (const float*)d_in[3];
    const float* Wo   = (const float*)d_in[4];
    const float* Wlat = (const float*)d_in[5];
    const float* gate = (const float*)d_in[6];
    float* out = (float*)d_out;

    static bool attr_done = false;
    if (!attr_done) {
        cudaFuncSetAttribute(lc_main, cudaFuncAttributeMaxDynamicSharedMemorySize, SMEM_BYTES);
        attr_done = true;
    }

    lc_setup<<<dim3(256, 2), 256>>>(Wq, Wk, Wv, Wo);
    lc_main<<<2048, THREADS, SMEM_BYTES>>>(h, Wlat, gate, out);
}

// round 8
// speedup vs baseline: 1.1094x; 1.1094x over previous
#include <cuda_runtime.h>
#include <cstdint>

// out = Wlat^T X  +  sigmoid(gate) * softmax(X Wa X^T) X Wb
//   Wa[k][n] = sum_e Wq[e,k] Wk[e,n] / 16     (vector-contiguous frags, g_Wa_f)
//   Wb[k][n] = sum_e Wo[n,e] Wv[e,k]          (vector-contiguous frags, g_Wb_f)
// B=8,T=2048,P=13,D=256. Warp = 1 token (16-row padded), 4 warps/CTA, 2 CTA/SM.

#define THREADS 128
#define SXR 260       // X smem row stride (fp32, 13 rows stored)
#define SCB 68        // chunk buffer stride (16 x 64)
#define SAT 20        // attn stride (16 x 16)
#define P1PAN 2048    // 32x64 panel: [(ks*4+q)*32 + lane] float4
#define P2PAN 4096    // 32x128 panel: [(ks*8+wv)*32 + lane] float4

#define SM_X 0                 // 4*13*260 = 13520
#define SM_P 13520             // 2*4096 = 8192 (double buffer, both phases)
#define SM_C 21712             // 4*16*68 = 4352
#define SM_A 26064             // 4*16*20 = 1280
#define SM_W 27344             // 320
#define SMEM_FLOATS 27664
#define SMEM_BYTES (SMEM_FLOATS * 4)   // 110656

__device__ float g_Wa_f[32 * P1PAN];   // panel (nc*8+kp)
__device__ float g_Wb_f[16 * P2PAN];   // panel (nh*8+dc*2+kp2)

__device__ __forceinline__ uint32_t f2tf(float x) {
    uint32_t r;
    asm("cvt.rna.tf32.f32 %0, %1;" : "=r"(r) : "f"(x));
    return r;
}
__device__ __forceinline__ float f2tff(float x) {
    return __uint_as_float(f2tf(x));
}

__device__ __forceinline__ void mma8(float* d,
                                     uint32_t a0, uint32_t a1, uint32_t a2, uint32_t a3,
                                     uint32_t b0, uint32_t b1) {
    asm volatile(
        "mma.sync.aligned.m16n8k8.row.col.f32.tf32.tf32.f32 "
        "{%0,%1,%2,%3},{%4,%5,%6,%7},{%8,%9},{%0,%1,%2,%3};\n"
        : "+f"(d[0]), "+f"(d[1]), "+f"(d[2]), "+f"(d[3])
        : "r"(a0), "r"(a1), "r"(a2), "r"(a3), "r"(b0), "r"(b1));
}

// ------------------------------- setup --------------------------------------
__global__ void lc_setup(const float* __restrict__ Wq, const float* __restrict__ Wk,
                         const float* __restrict__ Wv, const float* __restrict__ Wo) {
    int n = threadIdx.x;
    int k = blockIdx.x;
    if (blockIdx.y == 0) {
        float acc = 0.f;
        for (int e = 0; e < 256; ++e)
            acc += Wq[e * 256 + k] * Wk[e * 256 + n];
        acc *= (1.0f / 16.0f);
        int kp = k >> 5, r = k & 31;
        int ks = r >> 3, t7 = r & 7, tg = t7 & 3, j = t7 >> 2;
        int nc = n >> 6, nt = (n >> 3) & 7, g = n & 7;
        int q = nt >> 1, comp = (nt & 1) * 2 + j;
        g_Wa_f[(nc * 8 + kp) * P1PAN + (((ks * 4 + q) * 32 + g * 4 + tg) << 2) + comp] =
            f2tff(acc);
    } else {
        float acc = 0.f;
        for (int e = 0; e < 256; ++e)
            acc += Wo[n * 256 + e] * Wv[e * 256 + k];
        int dc = k >> 6, kp2 = (k >> 5) & 1, r = k & 31;
        int ks = r >> 3, t7 = r & 7, tg = t7 & 3, j = t7 >> 2;
        int nh = n >> 7, nt = (n >> 3) & 15, g = n & 7;
        int wv = nt >> 1, comp = (nt & 1) * 2 + j;
        g_Wb_f[(nh * 8 + dc * 2 + kp2) * P2PAN + (((ks * 8 + wv) * 32 + g * 4 + tg) << 2) + comp] =
            f2tff(acc);
    }
}

// -------------------------------- main --------------------------------------
__global__ void __launch_bounds__(THREADS, 2)
lc_main(const float* __restrict__ h, const float* __restrict__ Wlat,
        const float* __restrict__ gate, float* __restrict__ out) {
    extern __shared__ float smem[];
    const int tid = threadIdx.x;
    const int w = tid >> 5, lane = tid & 31;
    const int g = lane >> 2, tg = lane & 3;
    const long token = (long)blockIdx.x * 4 + w;
    const bool gok = (g < 5);   // row g+8 valid (<13)

    float* Xs = smem + SM_X + w * 13 * SXR;
    float* Cb = smem + SM_C + w * 16 * SCB;
    float* As = smem + SM_A + w * 16 * SAT;
    float* Wls = smem + SM_W;

    // ---- load X (13x256 fp32; no pad rows) ----
    const float* hx = h + token * 3328;
    for (int i = lane; i < 832; i += 32) {
        int row = i >> 6, c4 = (i & 63) << 2;
        *(float4*)(Xs + row * SXR + c4) = *(const float4*)(hx + row * 256 + c4);
    }
    for (int idx = tid; idx < 208; idx += THREADS) {
        int p = idx >> 4, r = idx & 15;
        Wls[p * 16 + r] = (r < 13) ? Wlat[p * 13 + r] : 0.f;
    }
    float sig;
    { float gv = gate[0]; sig = 1.f / (1.f + __expf(-gv)); }
    __syncthreads();

    // =================== phase 1: Y = X Wa, S = Y X^T ===================
    float s0[4] = {0, 0, 0, 0}, s1[4] = {0, 0, 0, 0};

    for (int nc = 0; nc < 4; ++nc) {
        float ya[8][4];
#pragma unroll
        for (int i = 0; i < 8; ++i)
#pragma unroll
            for (int j = 0; j < 4; ++j) ya[i][j] = 0.f;

        // initial pair (panels kp=0,1) -> buf0
        {
            const float4* src = (const float4*)(g_Wa_f + nc * 8 * P1PAN);
            float4* dst = (float4*)(smem + SM_P);
#pragma unroll
            for (int t = 0; t < 8; ++t) dst[tid + t * THREADS] = src[tid + t * THREADS];
        }
        __syncthreads();

        for (int pr = 0; pr < 4; ++pr) {
            float4 pf[8];
            if (pr < 3) {
                const float4* src = (const float4*)(g_Wa_f + (nc * 8 + (pr + 1) * 2) * P1PAN);
#pragma unroll
                for (int t = 0; t < 8; ++t) pf[t] = src[tid + t * THREADS];
            }
            const float* curb = smem + SM_P + (pr & 1) * P2PAN;
#pragma unroll
            for (int hf = 0; hf < 2; ++hf) {
                const float4* c4p = (const float4*)(curb + hf * P1PAN);
#pragma unroll
                for (int ks = 0; ks < 4; ++ks) {
                    int kc = pr * 64 + hf * 32 + ks * 8;
                    uint32_t a0 = f2tf(Xs[g * SXR + kc + tg]);
                    uint32_t a1 = gok ? f2tf(Xs[(g + 8) * SXR + kc + tg]) : 0u;
                    uint32_t a2 = f2tf(Xs[g * SXR + kc + tg + 4]);
                    uint32_t a3 = gok ? f2tf(Xs[(g + 8) * SXR + kc + tg + 4]) : 0u;
                    float4 f0 = c4p[(ks * 4 + 0) * 32 + lane];
                    float4 f1 = c4p[(ks * 4 + 1) * 32 + lane];
                    float4 f2v = c4p[(ks * 4 + 2) * 32 + lane];
                    float4 f3v = c4p[(ks * 4 + 3) * 32 + lane];
                    mma8(ya[0], a0, a1, a2, a3, __float_as_uint(f0.x), __float_as_uint(f0.y));
                    mma8(ya[1], a0, a1, a2, a3, __float_as_uint(f0.z), __float_as_uint(f0.w));
                    mma8(ya[2], a0, a1, a2, a3, __float_as_uint(f1.x), __float_as_uint(f1.y));
                    mma8(ya[3], a0, a1, a2, a3, __float_as_uint(f1.z), __float_as_uint(f1.w));
                    mma8(ya[4], a0, a1, a2, a3, __float_as_uint(f2v.x), __float_as_uint(f2v.y));
                    mma8(ya[5], a0, a1, a2, a3, __float_as_uint(f2v.z), __float_as_uint(f2v.w));
                    mma8(ya[6], a0, a1, a2, a3, __float_as_uint(f3v.x), __float_as_uint(f3v.y));
                    mma8(ya[7], a0, a1, a2, a3, __float_as_uint(f3v.z), __float_as_uint(f3v.w));
                }
            }
            if (pr < 3) {
                float4* nxt = (float4*)(smem + SM_P + ((pr + 1) & 1) * P2PAN);
#pragma unroll
                for (int t = 0; t < 8; ++t) nxt[tid + t * THREADS] = pf[t];
            }
            __syncthreads();
        }

        // Ychunk -> Cb (tf32), S += Ychunk * Xchunk^T
        __syncwarp();
#pragma unroll
        for (int nt = 0; nt < 8; ++nt) {
            int c = nt * 8 + 2 * tg;
            *(float2*)(Cb + g * SCB + c) = make_float2(f2tff(ya[nt][0]), f2tff(ya[nt][1]));
            *(float2*)(Cb + (g + 8) * SCB + c) = make_float2(f2tff(ya[nt][2]), f2tff(ya[nt][3]));
        }
        __syncwarp();
#pragma unroll
        for (int ks = 0; ks < 8; ++ks) {
            uint32_t a0 = __float_as_uint(Cb[g * SCB + ks * 8 + tg]);
            uint32_t a1 = __float_as_uint(Cb[(g + 8) * SCB + ks * 8 + tg]);
            uint32_t a2 = __float_as_uint(Cb[g * SCB + ks * 8 + tg + 4]);
            uint32_t a3 = __float_as_uint(Cb[(g + 8) * SCB + ks * 8 + tg + 4]);
            int xc = nc * 64 + ks * 8;
            uint32_t b0 = f2tf(Xs[g * SXR + xc + tg]);
            uint32_t b1 = f2tf(Xs[g * SXR + xc + tg + 4]);
            mma8(s0, a0, a1, a2, a3, b0, b1);
            uint32_t c0 = gok ? f2tf(Xs[(g + 8) * SXR + xc + tg]) : 0u;
            uint32_t c1 = gok ? f2tf(Xs[(g + 8) * SXR + xc + tg + 4]) : 0u;
            mma8(s1, a0, a1, a2, a3, c0, c1);
        }
        __syncwarp();
    }

    // =================== softmax over cols 0..12 (sig folded in) ============
    {
        int c0 = 2 * tg, c1 = 2 * tg + 1, c2 = 8 + 2 * tg, c3 = 9 + 2 * tg;
        bool v0 = c0 < 13, v1 = c1 < 13, v2 = c2 < 13, v3 = c3 < 13;
        const float NEG = -1e30f;
        float m0 = fmaxf(fmaxf(v0 ? s0[0] : NEG, v1 ? s0[1] : NEG),
                         fmaxf(v2 ? s1[0] : NEG, v3 ? s1[1] : NEG));
        float m1 = fmaxf(fmaxf(v0 ? s0[2] : NEG, v1 ? s0[3] : NEG),
                         fmaxf(v2 ? s1[2] : NEG, v3 ? s1[3] : NEG));
        m0 = fmaxf(m0, __shfl_xor_sync(0xffffffffu, m0, 1));
        m0 = fmaxf(m0, __shfl_xor_sync(0xffffffffu, m0, 2));
        m1 = fmaxf(m1, __shfl_xor_sync(0xffffffffu, m1, 1));
        m1 = fmaxf(m1, __shfl_xor_sync(0xffffffffu, m1, 2));
        float e00 = v0 ? __expf(s0[0] - m0) : 0.f;
        float e01 = v1 ? __expf(s0[1] - m0) : 0.f;
        float e02 = v2 ? __expf(s1[0] - m0) : 0.f;
        float e03 = v3 ? __expf(s1[1] - m0) : 0.f;
        float e10 = v0 ? __expf(s0[2] - m1) : 0.f;
        float e11 = v1 ? __expf(s0[3] - m1) : 0.f;
        float e12 = v2 ? __expf(s1[2] - m1) : 0.f;
        float e13 = v3 ? __expf(s1[3] - m1) : 0.f;
        float d0 = e00 + e01 + e02 + e03;
        float d1 = e10 + e11 + e12 + e13;
        d0 += __shfl_xor_sync(0xffffffffu, d0, 1);
        d0 += __shfl_xor_sync(0xffffffffu, d0, 2);
        d1 += __shfl_xor_sync(0xffffffffu, d1, 1);
        d1 += __shfl_xor_sync(0xffffffffu, d1, 2);
        float r0 = sig / d0, r1 = sig / d1;
        As[g * SAT + c0]       = f2tff(e00 * r0);
        As[g * SAT + c1]       = f2tff(e01 * r0);
        As[g * SAT + c2]       = f2tff(e02 * r0);
        As[g * SAT + c3]       = f2tff(e03 * r0);
        As[(g + 8) * SAT + c0] = f2tff(e10 * r1);
        As[(g + 8) * SAT + c1] = f2tff(e11 * r1);
        As[(g + 8) * SAT + c2] = f2tff(e12 * r1);
        As[(g + 8) * SAT + c3] = f2tff(e13 * r1);
        __syncwarp();
    }

    // =========== phase 2: Z = (sig*A) X (chunked), R = Z Wb, epilogue =======
    const long obase = token * 3328;
    for (int nh = 0; nh < 2; ++nh) {
        float ra[16][4];
#pragma unroll
        for (int i = 0; i < 16; ++i)
#pragma unroll
            for (int j = 0; j < 4; ++j) ra[i][j] = 0.f;

        // initial panel (ip=0) -> buf0
        {
            const float4* src = (const float4*)(g_Wb_f + nh * 8 * P2PAN);
            float4* dst = (float4*)(smem + SM_P);
#pragma unroll
            for (int t = 0; t < 8; ++t) dst[tid + t * THREADS] = src[tid + t * THREADS];
        }
        __syncthreads();

        int ip = 0;
        for (int dc = 0; dc < 4; ++dc) {
            // Zchunk = (sig*A) * X[:, dc*64 .. +64)
            float za[8][4];
#pragma unroll
            for (int i = 0; i < 8; ++i)
#pragma unroll
                for (int j = 0; j < 4; ++j) za[i][j] = 0.f;
#pragma unroll
            for (int ks = 0; ks < 2; ++ks) {
                uint32_t a0 = __float_as_uint(As[g * SAT + ks * 8 + tg]);
                uint32_t a1 = __float_as_uint(As[(g + 8) * SAT + ks * 8 + tg]);
                uint32_t a2 = __float_as_uint(As[g * SAT + ks * 8 + tg + 4]);
                uint32_t a3 = __float_as_uint(As[(g + 8) * SAT + ks * 8 + tg + 4]);
                int r0w = ks * 8 + tg;          // <= 11, always valid
                int r1w = ks * 8 + tg + 4;      // 13..15 invalid when ks=1, tg>0
                bool rok = r1w < 13;
#pragma unroll
                for (int nt = 0; nt < 8; ++nt) {
                    int xc = dc * 64 + nt * 8 + g;
                    uint32_t b0 = f2tf(Xs[r0w * SXR + xc]);
                    uint32_t b1 = rok ? f2tf(Xs[r1w * SXR + xc]) : 0u;
                    mma8(za[nt], a0, a1, a2, a3, b0, b1);
                }
            }
            __syncwarp();
#pragma unroll
            for (int nt = 0; nt < 8; ++nt) {
                int c = nt * 8 + 2 * tg;
                *(float2*)(Cb + g * SCB + c) = make_float2(f2tff(za[nt][0]), f2tff(za[nt][1]));
                *(float2*)(Cb + (g + 8) * SCB + c) = make_float2(f2tff(za[nt][2]), f2tff(za[nt][3]));
            }
            __syncwarp();

            for (int kp2 = 0; kp2 < 2; ++kp2, ++ip) {
                float4 pf[8];
                if (ip < 7) {
                    const float4* src = (const float4*)(g_Wb_f + (nh * 8 + ip + 1) * P2PAN);
#pragma unroll
                    for (int t = 0; t < 8; ++t) pf[t] = src[tid + t * THREADS];
                }
                const float4* c4p = (const float4*)(smem + SM_P + (ip & 1) * P2PAN);
#pragma unroll
                for (int ks = 0; ks < 4; ++ks) {
                    int kc = kp2 * 32 + ks * 8;
                    uint32_t a0 = __float_as_uint(Cb[g * SCB + kc + tg]);
                    uint32_t a1 = __float_as_uint(Cb[(g + 8) * SCB + kc + tg]);
                    uint32_t a2 = __float_as_uint(Cb[g * SCB + kc + tg + 4]);
                    uint32_t a3 = __float_as_uint(Cb[(g + 8) * SCB + kc + tg + 4]);
#pragma unroll
                    for (int wv = 0; wv < 8; ++wv) {
                        float4 f = c4p[(ks * 8 + wv) * 32 + lane];
                        mma8(ra[2 * wv], a0, a1, a2, a3,
                             __float_as_uint(f.x), __float_as_uint(f.y));
                        mma8(ra[2 * wv + 1], a0, a1, a2, a3,
                             __float_as_uint(f.z), __float_as_uint(f.w));
                    }
                }
                if (ip < 7) {
                    float4* nxt = (float4*)(smem + SM_P + ((ip + 1) & 1) * P2PAN);
#pragma unroll
                    for (int t = 0; t < 8; ++t) nxt[tid + t * THREADS] = pf[t];
                }
                __syncthreads();
            }
        }

        // ---- epilogue: exact fp32 residual accumulated into ra, then store ----
#pragma unroll 1
        for (int p = 0; p < 13; ++p) {
            float wg = Wls[p * 16 + g];
            float wg8 = Wls[p * 16 + g + 8];
#pragma unroll
            for (int nt = 0; nt < 16; ++nt) {
                int c = nh * 128 + nt * 8 + 2 * tg;
                float2 x = *(float2*)(Xs + p * SXR + c);
                ra[nt][0] += wg * x.x;
                ra[nt][1] += wg * x.y;
                ra[nt][2] += wg8 * x.x;
                ra[nt][3] += wg8 * x.y;
            }
        }
#pragma unroll
        for (int nt = 0; nt < 16; ++nt) {
            int c = nh * 128 + nt * 8 + 2 * tg;
            *(float2*)(out + obase + g * 256 + c) = make_float2(ra[nt][0], ra[nt][1]);
            if (gok)
                *(float2*)(out + obase + (g + 8) * 256 + c) = make_float2(ra[nt][2], ra[nt][3]);
        }
    }
}

// ------------------------------ launch --------------------------------------
extern "C" void kernel_launch(void* const* d_in, const int* in_sizes, int n_in,
                              void* d_out, int out_size) {
    const float* h    = (const float*)d_in[0];
    const float* Wq   = (const float*)d_in[1];
    const float* Wk   = (const float*)d_in[2];
    const float* Wv   = (const float*)d_in[3];
    const float* Wo   = (const float*)d_in[4];
    const float* Wlat = (const float*)d_in[5];
    const float* gate = (const float*)d_in[6];
    float* out = (float*)d_out;

    static bool attr_done = false;
    if (!attr_done) {
        cudaFuncSetAttribute(lc_main, cudaFuncAttributeMaxDynamicSharedMemorySize, SMEM_BYTES);
        attr_done = true;
    }

    lc_setup<<<dim3(256, 2), 256>>>(Wq, Wk, Wv, Wo);
    lc_main<<<4096, THREADS, SMEM_BYTES>>>(h, Wlat, gate, out);
}

// round 9
// speedup vs baseline: 1.6013x; 1.4434x over previous
#include <cuda_runtime.h>
#include <cuda_bf16.h>
#include <cstdint>

// out = Wlat^T X  +  sigmoid(gate) * softmax(X Wa X^T) X Wb
//   Wa[k][n] = sum_e Wq[e,k] Wk[e,n] / 16    (bf16 fragment-packed, g_Wa4)
//   Wb[k][n] = sum_e Wo[n,e] Wv[e,k]         (bf16 fragment-packed, g_Wb4)
// Big GEMMs (X*Wa, Z*Wb): bf16 m16n8k16.  S=Y*X^T and Z=A*X: tf32 m16n8k8.
// Residual: exact fp32. Warp = 1 token (16-row padded), 4 warps/CTA, 2 CTA/SM.

#define THREADS 128
#define SXR 260       // X smem row stride (fp32, 13 rows stored)
#define SCB 68        // chunk buffer stride (16 x 64)
#define SAT 20        // attn stride (16 x 16)

#define SM_X 0                 // 4*13*260 = 13520 floats
#define SM_P 13520             // 1024 uint4 = 4096 floats (2 panel buffers)
#define SM_C 17616             // 4*16*68 = 4352
#define SM_A 21968             // 4*16*20 = 1280
#define SM_W 23248             // 320
#define SMEM_FLOATS 23568
#define SMEM_BYTES (SMEM_FLOATS * 4)   // 94272

// Wa: 32 panels (nc*8+kp), panel = 32K x 64N bf16 = 256 uint4
// Wb: 16 panels (nh*8+dc*2+kp2), panel = 32K x 128N bf16 = 512 uint4
__device__ uint4 g_Wa4[32 * 256];
__device__ uint4 g_Wb4[16 * 512];

__device__ __forceinline__ uint32_t f2tf(float x) {
    uint32_t r;
    asm("cvt.rna.tf32.f32 %0, %1;" : "=r"(r) : "f"(x));
    return r;
}
__device__ __forceinline__ float f2tff(float x) {
    return __uint_as_float(f2tf(x));
}
// pack two consecutive fp32 (smem) into bf16x2 {lo=p[0], hi=p[1]}
__device__ __forceinline__ uint32_t pk2(const float* p) {
    float2 v = *(const float2*)p;
    uint32_t r;
    asm("cvt.rn.bf16x2.f32 %0, %1, %2;" : "=r"(r) : "f"(v.y), "f"(v.x));
    return r;
}

__device__ __forceinline__ void mma8(float* d,
                                     uint32_t a0, uint32_t a1, uint32_t a2, uint32_t a3,
                                     uint32_t b0, uint32_t b1) {
    asm volatile(
        "mma.sync.aligned.m16n8k8.row.col.f32.tf32.tf32.f32 "
        "{%0,%1,%2,%3},{%4,%5,%6,%7},{%8,%9},{%0,%1,%2,%3};\n"
        : "+f"(d[0]), "+f"(d[1]), "+f"(d[2]), "+f"(d[3])
        : "r"(a0), "r"(a1), "r"(a2), "r"(a3), "r"(b0), "r"(b1));
}
__device__ __forceinline__ void mmab(float* d,
                                     uint32_t a0, uint32_t a1, uint32_t a2, uint32_t a3,
                                     uint32_t b0, uint32_t b1) {
    asm volatile(
        "mma.sync.aligned.m16n8k16.row.col.f32.bf16.bf16.f32 "
        "{%0,%1,%2,%3},{%4,%5,%6,%7},{%8,%9},{%0,%1,%2,%3};\n"
        : "+f"(d[0]), "+f"(d[1]), "+f"(d[2]), "+f"(d[3])
        : "r"(a0), "r"(a1), "r"(a2), "r"(a3), "r"(b0), "r"(b1));
}

// ------------------------------- setup --------------------------------------
// Tiled 16x16 GEMM, scatters bf16 into packed fragment layout.
// grid (16,16,2), block (16,16). z=0: Wa, z=1: Wb.
__global__ void lc_setup(const float* __restrict__ Wq, const float* __restrict__ Wk,
                         const float* __restrict__ Wv, const float* __restrict__ Wo) {
    __shared__ float sA[16][17], sB[16][17];
    const int tx = threadIdx.x, ty = threadIdx.y;
    const int k0 = blockIdx.x * 16, n0 = blockIdx.y * 16;
    const bool isA = (blockIdx.z == 0);
    float acc = 0.f;
    for (int e0 = 0; e0 < 256; e0 += 16) {
        const float* Mp = isA ? Wq : Wv;
        sA[ty][tx] = Mp[(e0 + ty) * 256 + k0 + tx];         // [e][k]
        if (isA) sB[ty][tx] = Wk[(e0 + ty) * 256 + n0 + tx]; // [e][n]
        else     sB[tx][ty] = Wo[(n0 + ty) * 256 + e0 + tx]; // transpose -> [e][n]
        __syncthreads();
#pragma unroll
        for (int e = 0; e < 16; ++e) acc += sA[e][tx] * sB[e][ty];
        __syncthreads();
    }
    const int k = k0 + tx, n = n0 + ty;
    const int r = k & 31, s = r >> 4, rr = r & 15;
    const int half = rr >> 3, tg = (rr & 7) >> 1, j = rr & 1;
    if (isA) {
        acc *= (1.0f / 16.0f);
        int kp = k >> 5;
        int nc = n >> 6, nn = n & 63, nt = nn >> 3, g = nn & 7, q = nt >> 1;
        int u32idx = ((s * 4 + q) * 32 + g * 4 + tg) * 4 + (nt & 1) * 2 + half;
        ((__nv_bfloat16*)g_Wa4)[((nc * 8 + kp) * 1024 + u32idx) * 2 + j] =
            __float2bfloat16(acc);
    } else {
        int dc = k >> 6, kp2 = (k >> 5) & 1;
        int nh = n >> 7, nn = n & 127, nt = nn >> 3, g = nn & 7, q = nt >> 1;
        int u32idx = ((s * 8 + q) * 32 + g * 4 + tg) * 4 + (nt & 1) * 2 + half;
        ((__nv_bfloat16*)g_Wb4)[((nh * 8 + dc * 2 + kp2) * 2048 + u32idx) * 2 + j] =
            __float2bfloat16(acc);
    }
}

// -------------------------------- main --------------------------------------
__global__ void __launch_bounds__(THREADS, 2)
lc_main(const float* __restrict__ h, const float* __restrict__ Wlat,
        const float* __restrict__ gate, float* __restrict__ out) {
    extern __shared__ float smem[];
    const int tid = threadIdx.x;
    const int w = tid >> 5, lane = tid & 31;
    const int g = lane >> 2, tg = lane & 3;
    const long token = (long)blockIdx.x * 4 + w;
    const bool gok = (g < 5);   // row g+8 valid (<13)

    float* Xs = smem + SM_X + w * 13 * SXR;
    float* Cb = smem + SM_C + w * 16 * SCB;
    float* As = smem + SM_A + w * 16 * SAT;
    float* Wls = smem + SM_W;
    uint4* panq = (uint4*)(smem + SM_P);

    // ---- load X (13x256 fp32) ----
    const float* hx = h + token * 3328;
    for (int i = lane; i < 832; i += 32) {
        int row = i >> 6, c4 = (i & 63) << 2;
        *(float4*)(Xs + row * SXR + c4) = *(const float4*)(hx + row * 256 + c4);
    }
    for (int idx = tid; idx < 208; idx += THREADS) {
        int p = idx >> 4, r = idx & 15;
        Wls[p * 16 + r] = (r < 13) ? Wlat[p * 13 + r] : 0.f;
    }
    float sig;
    { float gv = gate[0]; sig = 1.f / (1.f + __expf(-gv)); }
    __syncthreads();

    // =========== phase 1: Y = X Wa (bf16), S = Y X^T (tf32) ===========
    float s0[4] = {0, 0, 0, 0}, s1[4] = {0, 0, 0, 0};

    for (int nc = 0; nc < 4; ++nc) {
        float ya[8][4];
#pragma unroll
        for (int i = 0; i < 8; ++i)
#pragma unroll
            for (int j = 0; j < 4; ++j) ya[i][j] = 0.f;

        // initial pair (panels kp=0,1) -> buf0  (512 uint4)
        {
            const uint4* src = g_Wa4 + nc * 8 * 256;
#pragma unroll
            for (int t = 0; t < 4; ++t) panq[tid + t * THREADS] = src[tid + t * THREADS];
        }
        __syncthreads();

        for (int pr = 0; pr < 4; ++pr) {
            uint4 pf[4];
            if (pr < 3) {
                const uint4* src = g_Wa4 + (nc * 8 + (pr + 1) * 2) * 256;
#pragma unroll
                for (int t = 0; t < 4; ++t) pf[t] = src[tid + t * THREADS];
            }
            const uint4* bufq = panq + (pr & 1) * 512;
#pragma unroll
            for (int hf = 0; hf < 2; ++hf) {
                const uint4* c4p = bufq + hf * 256;
#pragma unroll
                for (int s = 0; s < 2; ++s) {
                    int kc = pr * 64 + hf * 32 + s * 16;
                    uint32_t a0 = pk2(Xs + g * SXR + kc + 2 * tg);
                    uint32_t a1 = gok ? pk2(Xs + (g + 8) * SXR + kc + 2 * tg) : 0u;
                    uint32_t a2 = pk2(Xs + g * SXR + kc + 8 + 2 * tg);
                    uint32_t a3 = gok ? pk2(Xs + (g + 8) * SXR + kc + 8 + 2 * tg) : 0u;
#pragma unroll
                    for (int q = 0; q < 4; ++q) {
                        uint4 v = c4p[(s * 4 + q) * 32 + lane];
                        mmab(ya[2 * q], a0, a1, a2, a3, v.x, v.y);
                        mmab(ya[2 * q + 1], a0, a1, a2, a3, v.z, v.w);
                    }
                }
            }
            if (pr < 3) {
                uint4* nxt = panq + ((pr + 1) & 1) * 512;
#pragma unroll
                for (int t = 0; t < 4; ++t) nxt[tid + t * THREADS] = pf[t];
            }
            __syncthreads();
        }

        // Ychunk -> Cb (tf32), S += Ychunk * Xchunk^T
        __syncwarp();
#pragma unroll
        for (int nt = 0; nt < 8; ++nt) {
            int c = nt * 8 + 2 * tg;
            *(float2*)(Cb + g * SCB + c) = make_float2(f2tff(ya[nt][0]), f2tff(ya[nt][1]));
            *(float2*)(Cb + (g + 8) * SCB + c) = make_float2(f2tff(ya[nt][2]), f2tff(ya[nt][3]));
        }
        __syncwarp();
#pragma unroll
        for (int ks = 0; ks < 8; ++ks) {
            uint32_t a0 = __float_as_uint(Cb[g * SCB + ks * 8 + tg]);
            uint32_t a1 = __float_as_uint(Cb[(g + 8) * SCB + ks * 8 + tg]);
            uint32_t a2 = __float_as_uint(Cb[g * SCB + ks * 8 + tg + 4]);
            uint32_t a3 = __float_as_uint(Cb[(g + 8) * SCB + ks * 8 + tg + 4]);
            int xc = nc * 64 + ks * 8;
            uint32_t b0 = f2tf(Xs[g * SXR + xc + tg]);
            uint32_t b1 = f2tf(Xs[g * SXR + xc + tg + 4]);
            mma8(s0, a0, a1, a2, a3, b0, b1);
            uint32_t c0 = gok ? f2tf(Xs[(g + 8) * SXR + xc + tg]) : 0u;
            uint32_t c1 = gok ? f2tf(Xs[(g + 8) * SXR + xc + tg + 4]) : 0u;
            mma8(s1, a0, a1, a2, a3, c0, c1);
        }
        __syncwarp();
    }

    // =================== softmax over cols 0..12 (sig folded in) ============
    {
        int c0 = 2 * tg, c1 = 2 * tg + 1, c2 = 8 + 2 * tg, c3 = 9 + 2 * tg;
        bool v0 = c0 < 13, v1 = c1 < 13, v2 = c2 < 13, v3 = c3 < 13;
        const float NEG = -1e30f;
        float m0 = fmaxf(fmaxf(v0 ? s0[0] : NEG, v1 ? s0[1] : NEG),
                         fmaxf(v2 ? s1[0] : NEG, v3 ? s1[1] : NEG));
        float m1 = fmaxf(fmaxf(v0 ? s0[2] : NEG, v1 ? s0[3] : NEG),
                         fmaxf(v2 ? s1[2] : NEG, v3 ? s1[3] : NEG));
        m0 = fmaxf(m0, __shfl_xor_sync(0xffffffffu, m0, 1));
        m0 = fmaxf(m0, __shfl_xor_sync(0xffffffffu, m0, 2));
        m1 = fmaxf(m1, __shfl_xor_sync(0xffffffffu, m1, 1));
        m1 = fmaxf(m1, __shfl_xor_sync(0xffffffffu, m1, 2));
        float e00 = v0 ? __expf(s0[0] - m0) : 0.f;
        float e01 = v1 ? __expf(s0[1] - m0) : 0.f;
        float e02 = v2 ? __expf(s1[0] - m0) : 0.f;
        float e03 = v3 ? __expf(s1[1] - m0) : 0.f;
        float e10 = v0 ? __expf(s0[2] - m1) : 0.f;
        float e11 = v1 ? __expf(s0[3] - m1) : 0.f;
        float e12 = v2 ? __expf(s1[2] - m1) : 0.f;
        float e13 = v3 ? __expf(s1[3] - m1) : 0.f;
        float d0 = e00 + e01 + e02 + e03;
        float d1 = e10 + e11 + e12 + e13;
        d0 += __shfl_xor_sync(0xffffffffu, d0, 1);
        d0 += __shfl_xor_sync(0xffffffffu, d0, 2);
        d1 += __shfl_xor_sync(0xffffffffu, d1, 1);
        d1 += __shfl_xor_sync(0xffffffffu, d1, 2);
        float r0 = sig / d0, r1 = sig / d1;
        As[g * SAT + c0]       = f2tff(e00 * r0);
        As[g * SAT + c1]       = f2tff(e01 * r0);
        As[g * SAT + c2]       = f2tff(e02 * r0);
        As[g * SAT + c3]       = f2tff(e03 * r0);
        As[(g + 8) * SAT + c0] = f2tff(e10 * r1);
        As[(g + 8) * SAT + c1] = f2tff(e11 * r1);
        As[(g + 8) * SAT + c2] = f2tff(e12 * r1);
        As[(g + 8) * SAT + c3] = f2tff(e13 * r1);
        __syncwarp();
    }

    // ===== phase 2: Z = (sig*A) X (tf32), R = Z Wb (bf16), epilogue =====
    const long obase = token * 3328;
    for (int nh = 0; nh < 2; ++nh) {
        float ra[16][4];
#pragma unroll
        for (int i = 0; i < 16; ++i)
#pragma unroll
            for (int j = 0; j < 4; ++j) ra[i][j] = 0.f;

        // initial panel (ip=0) -> buf0 (512 uint4)
        {
            const uint4* src = g_Wb4 + nh * 8 * 512;
#pragma unroll
            for (int t = 0; t < 4; ++t) panq[tid + t * THREADS] = src[tid + t * THREADS];
        }
        __syncthreads();

        int ip = 0;
        for (int dc = 0; dc < 4; ++dc) {
            // Zchunk = (sig*A) * X[:, dc*64 .. +64)  (tf32)
            float za[8][4];
#pragma unroll
            for (int i = 0; i < 8; ++i)
#pragma unroll
                for (int j = 0; j < 4; ++j) za[i][j] = 0.f;
#pragma unroll
            for (int ks = 0; ks < 2; ++ks) {
                uint32_t a0 = __float_as_uint(As[g * SAT + ks * 8 + tg]);
                uint32_t a1 = __float_as_uint(As[(g + 8) * SAT + ks * 8 + tg]);
                uint32_t a2 = __float_as_uint(As[g * SAT + ks * 8 + tg + 4]);
                uint32_t a3 = __float_as_uint(As[(g + 8) * SAT + ks * 8 + tg + 4]);
                int r0w = ks * 8 + tg;
                int r1w = ks * 8 + tg + 4;
                bool rok = r1w < 13;
#pragma unroll
                for (int nt = 0; nt < 8; ++nt) {
                    int xc = dc * 64 + nt * 8 + g;
                    uint32_t b0 = f2tf(Xs[r0w * SXR + xc]);
                    uint32_t b1 = rok ? f2tf(Xs[r1w * SXR + xc]) : 0u;
                    mma8(za[nt], a0, a1, a2, a3, b0, b1);
                }
            }
            __syncwarp();
#pragma unroll
            for (int nt = 0; nt < 8; ++nt) {
                int c = nt * 8 + 2 * tg;
                *(float2*)(Cb + g * SCB + c) = make_float2(za[nt][0], za[nt][1]);
                *(float2*)(Cb + (g + 8) * SCB + c) = make_float2(za[nt][2], za[nt][3]);
            }
            __syncwarp();

            for (int kp2 = 0; kp2 < 2; ++kp2, ++ip) {
                uint4 pf[4];
                if (ip < 7) {
                    const uint4* src = g_Wb4 + (nh * 8 + ip + 1) * 512;
#pragma unroll
                    for (int t = 0; t < 4; ++t) pf[t] = src[tid + t * THREADS];
                }
                const uint4* c4p = panq + (ip & 1) * 512;
#pragma unroll
                for (int s = 0; s < 2; ++s) {
                    int kc = kp2 * 32 + s * 16;
                    uint32_t a0 = pk2(Cb + g * SCB + kc + 2 * tg);
                    uint32_t a1 = pk2(Cb + (g + 8) * SCB + kc + 2 * tg);
                    uint32_t a2 = pk2(Cb + g * SCB + kc + 8 + 2 * tg);
                    uint32_t a3 = pk2(Cb + (g + 8) * SCB + kc + 8 + 2 * tg);
#pragma unroll
                    for (int q = 0; q < 8; ++q) {
                        uint4 v = c4p[(s * 8 + q) * 32 + lane];
                        mmab(ra[2 * q], a0, a1, a2, a3, v.x, v.y);
                        mmab(ra[2 * q + 1], a0, a1, a2, a3, v.z, v.w);
                    }
                }
                if (ip < 7) {
                    uint4* nxt = panq + ((ip + 1) & 1) * 512;
#pragma unroll
                    for (int t = 0; t < 4; ++t) nxt[tid + t * THREADS] = pf[t];
                }
                __syncthreads();
            }
        }

        // ---- epilogue: exact fp32 residual accumulated into ra, then store ----
#pragma unroll 1
        for (int p = 0; p < 13; ++p) {
            float wg = Wls[p * 16 + g];
            float wg8 = Wls[p * 16 + g + 8];
#pragma unroll
            for (int nt = 0; nt < 16; ++nt) {
                int c = nh * 128 + nt * 8 + 2 * tg;
                float2 x = *(float2*)(Xs + p * SXR + c);
                ra[nt][0] += wg * x.x;
                ra[nt][1] += wg * x.y;
                ra[nt][2] += wg8 * x.x;
                ra[nt][3] += wg8 * x.y;
            }
        }
#pragma unroll
        for (int nt = 0; nt < 16; ++nt) {
            int c = nh * 128 + nt * 8 + 2 * tg;
            *(float2*)(out + obase + g * 256 + c) = make_float2(ra[nt][0], ra[nt][1]);
            if (gok)
                *(float2*)(out + obase + (g + 8) * 256 + c) = make_float2(ra[nt][2], ra[nt][3]);
        }
    }
}

// ------------------------------ launch --------------------------------------
extern "C" void kernel_launch(void* const* d_in, const int* in_sizes, int n_in,
                              void* d_out, int out_size) {
    const float* h    = (const float*)d_in[0];
    const float* Wq   = (const float*)d_in[1];
    const float* Wk   = (const float*)d_in[2];
    const float* Wv   = (const float*)d_in[3];
    const float* Wo   = (const float*)d_in[4];
    const float* Wlat = (const float*)d_in[5];
    const float* gate = (const float*)d_in[6];
    float* out = (float*)d_out;

    static bool attr_done = false;
    if (!attr_done) {
        cudaFuncSetAttribute(lc_main, cudaFuncAttributeMaxDynamicSharedMemorySize, SMEM_BYTES);
        attr_done = true;
    }

    lc_setup<<<dim3(16, 16, 2), dim3(16, 16)>>>(Wq, Wk, Wv, Wo);
    lc_main<<<4096, THREADS, SMEM_BYTES>>>(h, Wlat, gate, out);
}